// round 1
// baseline (speedup 1.0000x reference)
#include <cuda_runtime.h>

#define B_DIM   8
#define N_NODES 1600
#define V_DIM   256
#define F_DIM   256
#define ROWS    32
#define JT      64

// Scratch (allocation-free: device globals)
__device__ float g_Wh [B_DIM * N_NODES * F_DIM];
__device__ float g_Wh1[B_DIM * N_NODES];
__device__ float g_Wh2[B_DIM * N_NODES];

__device__ __forceinline__ void fma2(unsigned long long& d,
                                     unsigned long long a,
                                     unsigned long long b) {
    asm("fma.rn.f32x2 %0, %1, %2, %0;" : "+l"(d) : "l"(a), "l"(b));
}

// ---------------------------------------------------------------------------
// Kernel 1: Wh[b,n,f] = sum_v x[b,n,v] * W[f,v] + bW[f]
// One CTA = 32 rows of (B*N), 256 threads = one f per thread.
// ---------------------------------------------------------------------------
__global__ __launch_bounds__(256) void k_gemm1(const float* __restrict__ x,
                                               const float* __restrict__ W,
                                               const float* __restrict__ bW) {
    __shared__ __align__(16) float xs[ROWS][V_DIM];   // 32 KB
    __shared__ float WsT[32][257];                    // padded, ~33 KB
    const int f  = threadIdx.x;
    const long m0 = (long)blockIdx.x * ROWS;

    for (int r = 0; r < ROWS; r++)
        xs[r][f] = x[(m0 + r) * V_DIM + f];

    float acc[ROWS];
#pragma unroll
    for (int r = 0; r < ROWS; r++) acc[r] = 0.f;
    const float bv = bW[f];

    const int kk  = f & 31;
    const int fg0 = f >> 5;

    for (int v0 = 0; v0 < V_DIM; v0 += 32) {
        __syncthreads();
        // stage W[:, v0:v0+32] transposed: WsT[kk][fg] = W[fg][v0+kk]
#pragma unroll
        for (int p = 0; p < 32; p++) {
            int fg = fg0 + p * 8;
            WsT[kk][fg] = W[fg * V_DIM + v0 + kk];
        }
        __syncthreads();

        float wreg[32];
#pragma unroll
        for (int k = 0; k < 32; k++) wreg[k] = WsT[k][f];

#pragma unroll
        for (int r = 0; r < ROWS; r++) {
#pragma unroll
            for (int k4 = 0; k4 < 8; k4++) {
                float4 xv = *(const float4*)&xs[r][v0 + k4 * 4];
                acc[r] += xv.x * wreg[k4 * 4 + 0];
                acc[r] += xv.y * wreg[k4 * 4 + 1];
                acc[r] += xv.z * wreg[k4 * 4 + 2];
                acc[r] += xv.w * wreg[k4 * 4 + 3];
            }
        }
    }

    for (int r = 0; r < ROWS; r++)
        g_Wh[(m0 + r) * F_DIM + f] = acc[r] + bv;
}

// ---------------------------------------------------------------------------
// Kernel 1b: Wh1 = Wh . ai + bi ; Wh2 = Wh . aj + bj   (warp per row)
// ---------------------------------------------------------------------------
__global__ __launch_bounds__(256) void k_proj(const float* __restrict__ ai,
                                              const float* __restrict__ bi,
                                              const float* __restrict__ aj,
                                              const float* __restrict__ bj) {
    int gwarp = (blockIdx.x * blockDim.x + threadIdx.x) >> 5;
    int lane  = threadIdx.x & 31;
    if (gwarp >= B_DIM * N_NODES) return;
    const float* row = &g_Wh[(long)gwarp * F_DIM];
    float s1 = 0.f, s2 = 0.f;
#pragma unroll
    for (int k = lane; k < F_DIM; k += 32) {
        float v = row[k];
        s1 += v * ai[k];
        s2 += v * aj[k];
    }
#pragma unroll
    for (int o = 16; o; o >>= 1) {
        s1 += __shfl_xor_sync(0xFFFFFFFFu, s1, o);
        s2 += __shfl_xor_sync(0xFFFFFFFFu, s2, o);
    }
    if (lane == 0) {
        g_Wh1[gwarp] = s1 + bi[0];
        g_Wh2[gwarp] = s2 + bj[0];
    }
}

// ---------------------------------------------------------------------------
// Kernel 2: masked-softmax attention + att@Wh + ELU (flash-style, fused)
// Grid: (N/32, B). CTA handles 32 i-rows, thread = f column.
// ---------------------------------------------------------------------------
__global__ __launch_bounds__(256) void k_attn(const int* __restrict__ adj,
                                              float* __restrict__ out) {
    __shared__ float Wh2s[N_NODES];
    __shared__ float Wh1s[ROWS], ms[ROWS], invls[ROWS];
    __shared__ __align__(16) float wsm[JT][36];   // [j][r], padded: cf writes, 16B reads

    const int tid = threadIdx.x;
    const int b   = blockIdx.y;
    const int i0  = blockIdx.x * ROWS;

    for (int j = tid; j < N_NODES; j += 256)
        Wh2s[j] = g_Wh2[b * N_NODES + j];
    if (tid < ROWS)
        Wh1s[tid] = g_Wh1[b * N_NODES + i0 + tid];
    __syncthreads();

    // ---- Phase 1: per-row softmax stats (max, sum of exp) ----
    const int warp = tid >> 5, lane = tid & 31;
    for (int rr = 0; rr < 4; rr++) {
        int r = warp * 4 + rr;
        float wh1 = Wh1s[r];
        const int* arow = adj + (long)(i0 + r) * N_NODES;
        float m = -1e30f;
        for (int j = lane; j < N_NODES; j += 32) {
            float e = wh1 + Wh2s[j];
            e = e > 0.f ? e : 0.2f * e;
            float s = (arow[j] > 0) ? e : -1e9f;
            m = fmaxf(m, s);
        }
#pragma unroll
        for (int o = 16; o; o >>= 1) m = fmaxf(m, __shfl_xor_sync(0xFFFFFFFFu, m, o));
        float sum = 0.f;
        for (int j = lane; j < N_NODES; j += 32) {
            float e = wh1 + Wh2s[j];
            e = e > 0.f ? e : 0.2f * e;
            float s = (arow[j] > 0) ? e : -1e9f;
            sum += __expf(s - m);
        }
#pragma unroll
        for (int o = 16; o; o >>= 1) sum += __shfl_xor_sync(0xFFFFFFFFu, sum, o);
        if (lane == 0) { ms[r] = m; invls[r] = 1.f / sum; }
    }
    __syncthreads();

    // ---- Phase 2: stream j-tiles, accumulate h_hat with packed f32x2 FMA ----
    const int f  = tid;
    const int rw = tid >> 3;        // row this thread computes weights for
    const int j8 = tid & 7;
    const float wh1w = Wh1s[rw];
    const float mw   = ms[rw];
    const float ilw  = invls[rw];
    const int*  arw  = adj + (long)(i0 + rw) * N_NODES;
    const float* WhB = g_Wh + (long)b * N_NODES * F_DIM;

    unsigned long long acc2[16];
#pragma unroll
    for (int r2 = 0; r2 < 16; r2++) acc2[r2] = 0ull;

    for (int jt = 0; jt < N_NODES; jt += JT) {
        __syncthreads();
        // weights for this tile: wsm[jj][r] = exp(s-m)/l  (conflict-free writes)
#pragma unroll
        for (int k = 0; k < JT / 8; k++) {
            int jj = j8 + k * 8;
            int j  = jt + jj;
            float e = wh1w + Wh2s[j];
            e = e > 0.f ? e : 0.2f * e;
            float s = (arw[j] > 0) ? e : -1e9f;
            wsm[jj][rw] = __expf(s - mw) * ilw;
        }
        __syncthreads();

#pragma unroll 4
        for (int jj = 0; jj < JT; jj++) {
            float whv = WhB[(jt + jj) * F_DIM + f];      // coalesced, L2-hot
            float2 wp = make_float2(whv, whv);
            unsigned long long wpu = *(unsigned long long*)&wp;
#pragma unroll
            for (int r4 = 0; r4 < 8; r4++) {
                ulonglong2 wv = *(const ulonglong2*)&wsm[jj][4 * r4];  // 4 rows / LDS.128
                fma2(acc2[2 * r4 + 0], wv.x, wpu);
                fma2(acc2[2 * r4 + 1], wv.y, wpu);
            }
        }
    }

    // ---- Epilogue: ELU + store ----
#pragma unroll
    for (int r2 = 0; r2 < 16; r2++) {
        float2 a = *(float2*)&acc2[r2];
        float y0 = a.x > 0.f ? a.x : (__expf(a.x) - 1.f);
        float y1 = a.y > 0.f ? a.y : (__expf(a.y) - 1.f);
        out[((long)b * N_NODES + i0 + 2 * r2 + 0) * F_DIM + f] = y0;
        out[((long)b * N_NODES + i0 + 2 * r2 + 1) * F_DIM + f] = y1;
    }
}

// ---------------------------------------------------------------------------
extern "C" void kernel_launch(void* const* d_in, const int* in_sizes, int n_in,
                              void* d_out, int out_size) {
    const float* h   = (const float*)d_in[0];
    const int*   adj = (const int*)  d_in[1];
    const float* W   = (const float*)d_in[2];
    const float* bW  = (const float*)d_in[3];
    const float* ai  = (const float*)d_in[4];
    const float* bi  = (const float*)d_in[5];
    const float* aj  = (const float*)d_in[6];
    const float* bj  = (const float*)d_in[7];
    float* out = (float*)d_out;

    k_gemm1<<<(B_DIM * N_NODES) / ROWS, 256>>>(h, W, bW);
    k_proj<<<(B_DIM * N_NODES * 32) / 256, 256>>>(ai, bi, aj, bj);
    dim3 g2(N_NODES / ROWS, B_DIM);
    k_attn<<<g2, 256>>>(adj, out);
}

// round 4
// speedup vs baseline: 1.8226x; 1.8226x over previous
#include <cuda_runtime.h>
#include <cuda_fp16.h>
#include <cstdint>

#define BB      8
#define NODES   1600
#define VD      256
#define FD      256
#define KCH     32             // K chunk
#define NCH     (NODES / KCH)  // 50
#define STAGE_B 30720          // Ahi 5120 + Alo 5120 + Bhi 10240 + Blo 10240
#define SMEM_DYN (2 * STAGE_B)

// ---------------- scratch (device globals; allocation-free) ----------------
__device__ __align__(128) float  g_Wh  [BB * NODES * FD];
__device__ float                 g_Wh1 [BB * NODES];
__device__ float                 g_Wh2 [BB * NODES];
__device__ __align__(128) __half g_WhT_hi[BB * FD * NODES];
__device__ __align__(128) __half g_WhT_lo[BB * FD * NODES];
__device__ __align__(128) __half g_P_hi[(size_t)BB * NODES * NODES];
__device__ __align__(128) __half g_P_lo[(size_t)BB * NODES * NODES];

// ---------------- PTX helpers (sm_80-era only; NO tcgen05) ----------------
__device__ __forceinline__ uint32_t smem_u32(const void* p) {
    uint32_t a;
    asm("{ .reg .u64 t; cvta.to.shared.u64 t, %1; cvt.u32.u64 %0, t; }" : "=r"(a) : "l"(p));
    return a;
}
__device__ __forceinline__ void cp16(uint32_t dst, const void* src) {
    asm volatile("cp.async.cg.shared.global [%0], [%1], 16;" :: "r"(dst), "l"(src) : "memory");
}
#define CP_COMMIT() asm volatile("cp.async.commit_group;" ::: "memory")
#define CP_WAIT1()  asm volatile("cp.async.wait_group 1;" ::: "memory")
#define CP_WAIT0()  asm volatile("cp.async.wait_group 0;" ::: "memory")

__device__ __forceinline__ void ldmx4(uint32_t* r, uint32_t addr) {
    asm volatile("ldmatrix.sync.aligned.m8n8.x4.shared.b16 {%0,%1,%2,%3}, [%4];"
                 : "=r"(r[0]), "=r"(r[1]), "=r"(r[2]), "=r"(r[3]) : "r"(addr));
}
__device__ __forceinline__ void mma16816(float* c, const uint32_t* a,
                                         uint32_t b0, uint32_t b1) {
    asm volatile(
        "mma.sync.aligned.m16n8k16.row.col.f32.f16.f16.f32 "
        "{%0,%1,%2,%3}, {%4,%5,%6,%7}, {%8,%9}, {%0,%1,%2,%3};"
        : "+f"(c[0]), "+f"(c[1]), "+f"(c[2]), "+f"(c[3])
        : "r"(a[0]), "r"(a[1]), "r"(a[2]), "r"(a[3]), "r"(b0), "r"(b1));
}

// ---------------------------------------------------------------------------
// Kernel 1: Wh = x @ W^T + bW   (fp32; known good)
// ---------------------------------------------------------------------------
__global__ __launch_bounds__(256) void k_gemm1(const float* __restrict__ x,
                                               const float* __restrict__ W,
                                               const float* __restrict__ bW) {
    __shared__ __align__(16) float xs[32][VD];
    __shared__ float WsT[32][257];
    const int f = threadIdx.x;
    const long m0 = (long)blockIdx.x * 32;

    for (int r = 0; r < 32; r++)
        xs[r][f] = x[(m0 + r) * VD + f];

    float acc[32];
#pragma unroll
    for (int r = 0; r < 32; r++) acc[r] = 0.f;
    const float bv = bW[f];
    const int kk = f & 31, fg0 = f >> 5;

    for (int v0 = 0; v0 < VD; v0 += 32) {
        __syncthreads();
#pragma unroll
        for (int p = 0; p < 32; p++) {
            int fg = fg0 + p * 8;
            WsT[kk][fg] = W[fg * VD + v0 + kk];
        }
        __syncthreads();
        float wreg[32];
#pragma unroll
        for (int k = 0; k < 32; k++) wreg[k] = WsT[k][f];
#pragma unroll
        for (int r = 0; r < 32; r++) {
#pragma unroll
            for (int k4 = 0; k4 < 8; k4++) {
                float4 xv = *(const float4*)&xs[r][v0 + k4 * 4];
                acc[r] += xv.x * wreg[k4 * 4 + 0];
                acc[r] += xv.y * wreg[k4 * 4 + 1];
                acc[r] += xv.z * wreg[k4 * 4 + 2];
                acc[r] += xv.w * wreg[k4 * 4 + 3];
            }
        }
    }
    for (int r = 0; r < 32; r++)
        g_Wh[(m0 + r) * FD + f] = acc[r] + bv;
}

// ---------------------------------------------------------------------------
// Kernel 1b: Wh1/Wh2 projections (warp per row)
// ---------------------------------------------------------------------------
__global__ __launch_bounds__(256) void k_proj(const float* __restrict__ ai,
                                              const float* __restrict__ bi,
                                              const float* __restrict__ aj,
                                              const float* __restrict__ bj) {
    int gwarp = (blockIdx.x * blockDim.x + threadIdx.x) >> 5;
    int lane = threadIdx.x & 31;
    if (gwarp >= BB * NODES) return;
    const float* row = &g_Wh[(long)gwarp * FD];
    float s1 = 0.f, s2 = 0.f;
#pragma unroll
    for (int k = lane; k < FD; k += 32) {
        float v = row[k];
        s1 += v * ai[k];
        s2 += v * aj[k];
    }
#pragma unroll
    for (int o = 16; o; o >>= 1) {
        s1 += __shfl_xor_sync(0xFFFFFFFFu, s1, o);
        s2 += __shfl_xor_sync(0xFFFFFFFFu, s2, o);
    }
    if (lane == 0) {
        g_Wh1[gwarp] = s1 + bi[0];
        g_Wh2[gwarp] = s2 + bj[0];
    }
}

// ---------------------------------------------------------------------------
// Kernel 1c: WhT_hi/lo[b][f][j] = fp16-split(Wh[b][j][f])  (32x32 transpose)
// ---------------------------------------------------------------------------
__global__ __launch_bounds__(256) void k_trans() {
    __shared__ float t[32][33];
    const int b = blockIdx.z, f0 = blockIdx.y * 32, j0 = blockIdx.x * 32;
    const int tx = threadIdx.x & 31, ty = threadIdx.x >> 5;
#pragma unroll
    for (int k = 0; k < 4; k++) {
        int jj = ty + 8 * k;
        t[jj][tx] = g_Wh[((long)(b * NODES) + (j0 + jj)) * FD + f0 + tx];
    }
    __syncthreads();
#pragma unroll
    for (int k = 0; k < 4; k++) {
        int ff = ty + 8 * k;
        float v = t[tx][ff];
        __half hi = __float2half_rn(v);
        __half lo = __float2half_rn(v - __half2float(hi));
        size_t o = ((size_t)(b * FD + f0 + ff)) * NODES + j0 + tx;
        g_WhT_hi[o] = hi;
        g_WhT_lo[o] = lo;
    }
}

// ---------------------------------------------------------------------------
// Kernel 2: masked softmax -> P_hi/P_lo (fp16 split), half2 stores
// ---------------------------------------------------------------------------
__global__ __launch_bounds__(256) void k_soft(const int* __restrict__ adj) {
    __shared__ float Wh2s[NODES];
    __shared__ float Wh1s[32], ms[32], ils[32];
    const int tid = threadIdx.x, b = blockIdx.y;
    const int i0 = blockIdx.x * 32;

    for (int j = tid; j < NODES; j += 256)
        Wh2s[j] = g_Wh2[b * NODES + j];
    if (tid < 32)
        Wh1s[tid] = g_Wh1[b * NODES + i0 + tid];
    __syncthreads();

    const int warp = tid >> 5, lane = tid & 31;
    for (int rr = 0; rr < 4; rr++) {
        int r = warp * 4 + rr;
        float wh1 = Wh1s[r];
        const int* arow = adj + (size_t)(i0 + r) * NODES;
        float m = -1e30f;
        for (int j = lane; j < NODES; j += 32) {
            float e = wh1 + Wh2s[j];
            e = e > 0.f ? e : 0.2f * e;
            float s = (arow[j] > 0) ? e : -1e9f;
            m = fmaxf(m, s);
        }
#pragma unroll
        for (int o = 16; o; o >>= 1) m = fmaxf(m, __shfl_xor_sync(0xFFFFFFFFu, m, o));
        float sum = 0.f;
        for (int j = lane; j < NODES; j += 32) {
            float e = wh1 + Wh2s[j];
            e = e > 0.f ? e : 0.2f * e;
            float s = (arow[j] > 0) ? e : -1e9f;
            sum += __expf(s - m);
        }
#pragma unroll
        for (int o = 16; o; o >>= 1) sum += __shfl_xor_sync(0xFFFFFFFFu, sum, o);
        if (lane == 0) { ms[r] = m; ils[r] = 1.f / sum; }
    }
    __syncthreads();

    for (int rr = 0; rr < 4; rr++) {
        int r = warp * 4 + rr;
        int i = i0 + r;
        float wh1 = Wh1s[r], m = ms[r], il = ils[r];
        const int* arow = adj + (size_t)i * NODES;
        size_t pb = ((size_t)(b * NODES + i)) * NODES;
        for (int jj = lane; jj < NODES / 2; jj += 32) {
            int j = 2 * jj;
            float e0 = wh1 + Wh2s[j];
            float e1 = wh1 + Wh2s[j + 1];
            e0 = e0 > 0.f ? e0 : 0.2f * e0;
            e1 = e1 > 0.f ? e1 : 0.2f * e1;
            float s0 = (arow[j] > 0) ? e0 : -1e9f;
            float s1 = (arow[j + 1] > 0) ? e1 : -1e9f;
            float w0 = __expf(s0 - m) * il;
            float w1 = __expf(s1 - m) * il;
            __half h0 = __float2half_rn(w0);
            __half h1 = __float2half_rn(w1);
            __half l0 = __float2half_rn(w0 - __half2float(h0));
            __half l1 = __float2half_rn(w1 - __half2float(h1));
            *(__half2*)&g_P_hi[pb + j] = __halves2half2(h0, h1);
            *(__half2*)&g_P_lo[pb + j] = __halves2half2(l0, l1);
        }
    }
}

// ---------------------------------------------------------------------------
// Kernel 3: h_hat = P @ Wh^T via mma.sync fp16 hi/lo (3 terms) + ELU
// CTA 64(M) x 128(N); 8 warps 2x4; warp tile 32x32; K chunks of 32, 2-stage.
// smem rows padded to 80B -> (5r mod 8) bank permutation, ldmatrix conflict-free.
// ---------------------------------------------------------------------------
__global__ __launch_bounds__(256) void k_mma2(float* __restrict__ out) {
    extern __shared__ __align__(128) char dsm[];
    const int tid = threadIdx.x, wid = tid >> 5, lane = tid & 31;
    const int m0 = blockIdx.x * 64, n0 = blockIdx.y * 128, b = blockIdx.z;
    const int wm = wid >> 2, wn = wid & 3;

    const __half* Ah = g_P_hi + ((size_t)(b * NODES + m0)) * NODES;
    const __half* Al = g_P_lo + ((size_t)(b * NODES + m0)) * NODES;
    const __half* Bh = g_WhT_hi + ((size_t)b * FD + n0) * NODES;
    const __half* Bl = g_WhT_lo + ((size_t)b * FD + n0) * NODES;

    const uint32_t s0 = smem_u32(dsm);

    // ---- async-load one K-chunk into a stage ----
    auto load_chunk = [&](int c) {
        const uint32_t st = s0 + (c & 1) * STAGE_B;
        const int jt = c * KCH;
        // A hi/lo: 64 rows x 64B (4 x 16B), padded row stride 80B
        {
            int row = tid >> 2, cc = tid & 3;                    // 256 = 64*4
            uint32_t o = (uint32_t)(row * 80 + cc * 16);
            const size_t go = (size_t)row * NODES + jt + cc * 8;
            cp16(st + o,        Ah + go);
            cp16(st + 5120 + o, Al + go);
        }
        // B hi/lo: 128 rows x 64B
        for (int t = tid; t < 512; t += 256) {
            int row = t >> 2, cc = t & 3;
            uint32_t o = (uint32_t)(row * 80 + cc * 16);
            const size_t go = (size_t)row * NODES + jt + cc * 8;
            cp16(st + 10240 + o, Bh + go);
            cp16(st + 20480 + o, Bl + go);
        }
        CP_COMMIT();
    };

    float acc[2][4][4];
#pragma unroll
    for (int mt = 0; mt < 2; mt++)
#pragma unroll
        for (int nt = 0; nt < 4; nt++)
#pragma unroll
            for (int q = 0; q < 4; q++) acc[mt][nt][q] = 0.f;

    // ldmatrix per-lane row/col components
    const int aRow = wm * 32 + (lane & 7) + ((lane >> 3) & 1) * 8;
    const int aC16 = ((lane >> 4) & 1) * 16;
    const int bRow = wn * 32 + (lane & 7) + ((lane >> 4) & 1) * 8;   // includes wn offset
    const int bC16 = ((lane >> 3) & 1) * 16;

    load_chunk(0);

    for (int c = 0; c < NCH; c++) {
        if (c + 1 < NCH) { load_chunk(c + 1); CP_WAIT1(); }
        else            { CP_WAIT0(); }
        __syncthreads();

        const uint32_t st = s0 + (c & 1) * STAGE_B;
#pragma unroll
        for (int ks = 0; ks < 2; ks++) {
            const int koff = ks * 32;
            uint32_t ah[2][4], al[2][4], bh[2][4], bl[2][4];
#pragma unroll
            for (int mt = 0; mt < 2; mt++) {
                uint32_t ao = st + (uint32_t)((aRow + mt * 16) * 80 + aC16 + koff);
                ldmx4(ah[mt], ao);
                ldmx4(al[mt], ao + 5120);
            }
#pragma unroll
            for (int p = 0; p < 2; p++) {
                // FIX: bRow already contains wn*32 — do not add it twice.
                uint32_t bo = st + 10240 +
                              (uint32_t)((bRow + p * 16) * 80 + bC16 + koff);
                ldmx4(bh[p], bo);
                ldmx4(bl[p], bo + 10240);
            }
#pragma unroll
            for (int mt = 0; mt < 2; mt++) {
#pragma unroll
                for (int nt = 0; nt < 4; nt++) {
                    const int p = nt >> 1, hf = (nt & 1) * 2;
                    mma16816(acc[mt][nt], ah[mt], bh[p][hf], bh[p][hf + 1]);
                    mma16816(acc[mt][nt], ah[mt], bl[p][hf], bl[p][hf + 1]);
                    mma16816(acc[mt][nt], al[mt], bh[p][hf], bh[p][hf + 1]);
                }
            }
        }
        __syncthreads();
    }

    // ---- epilogue: ELU + store ----
#pragma unroll
    for (int mt = 0; mt < 2; mt++) {
#pragma unroll
        for (int nt = 0; nt < 4; nt++) {
            const int m = m0 + wm * 32 + mt * 16 + (lane >> 2);
            const int n = n0 + wn * 32 + nt * 8 + (lane & 3) * 2;
            float* op = out + ((size_t)(b * NODES) + m) * FD + n;
            float d0 = acc[mt][nt][0], d1 = acc[mt][nt][1];
            float d2 = acc[mt][nt][2], d3 = acc[mt][nt][3];
            float2 v0, v1;
            v0.x = d0 > 0.f ? d0 : (__expf(d0) - 1.f);
            v0.y = d1 > 0.f ? d1 : (__expf(d1) - 1.f);
            v1.x = d2 > 0.f ? d2 : (__expf(d2) - 1.f);
            v1.y = d3 > 0.f ? d3 : (__expf(d3) - 1.f);
            *(float2*)op = v0;
            *(float2*)(op + 8 * FD) = v1;
        }
    }
}

// ---------------------------------------------------------------------------
extern "C" void kernel_launch(void* const* d_in, const int* in_sizes, int n_in,
                              void* d_out, int out_size) {
    const float* h   = (const float*)d_in[0];
    const int*   adj = (const int*)  d_in[1];
    const float* W   = (const float*)d_in[2];
    const float* bW  = (const float*)d_in[3];
    const float* ai  = (const float*)d_in[4];
    const float* bi  = (const float*)d_in[5];
    const float* aj  = (const float*)d_in[6];
    const float* bj  = (const float*)d_in[7];
    float* out = (float*)d_out;

    cudaFuncSetAttribute(k_mma2, cudaFuncAttributeMaxDynamicSharedMemorySize, SMEM_DYN);

    k_gemm1<<<(BB * NODES) / 32, 256>>>(h, W, bW);
    k_proj<<<(BB * NODES * 32) / 256, 256>>>(ai, bi, aj, bj);
    dim3 gt(NODES / 32, FD / 32, BB);
    k_trans<<<gt, 256>>>();
    dim3 gs(NODES / 32, BB);
    k_soft<<<gs, 256>>>(adj);
    dim3 gm(NODES / 64, FD / 128, BB);
    k_mma2<<<gm, 256, SMEM_DYN>>>(out);
}